// round 14
// baseline (speedup 1.0000x reference)
#include <cuda_runtime.h>
#include <stdint.h>

// Problem constants (fixed by the reference problem definition)
#define FEAT_DIM 128
#define BATCH    4
#define NY       512
#define NX       512
#define NYNX     (NY * NX)
#define NPIX     (BATCH * NYNX)      // 1,048,576

#define XT    128      // x-tile per block (4 stages of 32)
#define SPX   32       // pixels per stage
#define NBUF  3        // ring buffers: smem ~50KB -> 4 blocks/SM = 64 warps
#define NTH   512      // 16 warps

// 4 MB scratch: winner map. INVARIANT: all-zero on entry to kernel_launch.
//  - zero at module load (device globals are zero-initialized)
//  - k_argmax writes (voxel_index + 1) via atomicMax (last-write-wins == max idx)
//  - k_gather restores every nonzero entry it consumed back to 0
__device__ int g_map[NPIX];

// ---------------------------------------------------------------------------
// cp.async helpers: 16B global->shared, src_size=0 => zero-fill (empty pixels)
// ---------------------------------------------------------------------------
__device__ __forceinline__ uint32_t smem_u32(const void* p) {
    return (uint32_t)__cvta_generic_to_shared(p);
}
__device__ __forceinline__ void cp_async16(uint32_t dst, const void* src, int src_size) {
    asm volatile("cp.async.cg.shared.global [%0], [%1], 16, %2;\n"
                 :: "r"(dst), "l"(src), "r"(src_size));
}
__device__ __forceinline__ void cp_commit() {
    asm volatile("cp.async.commit_group;\n" ::: "memory");
}
template <int N>
__device__ __forceinline__ void cp_wait() {
    asm volatile("cp.async.wait_group %0;\n" :: "n"(N) : "memory");
}

// ---------------------------------------------------------------------------
// Kernel 1: winner per pixel.  coors: [N,4] int32 (b, z, y, x)
// 4 voxels/thread: 4 independent __ldcs int4 loads issued back-to-back
// (MLP=4), then 4 fire-and-forget REDs. Tail guarded separately so the hot
// path has no per-load branches (R10's mistake).
// ---------------------------------------------------------------------------
__global__ __launch_bounds__(512)
void k_argmax_map(const int* __restrict__ coors, int n) {
    int i = (blockIdx.x * blockDim.x + threadIdx.x) * 4;
    const int4* c4 = reinterpret_cast<const int4*>(coors);
    if (i + 3 < n) {
        int4 c0 = __ldcs(c4 + i);
        int4 c1 = __ldcs(c4 + i + 1);
        int4 c2 = __ldcs(c4 + i + 2);
        int4 c3 = __ldcs(c4 + i + 3);
        atomicMax(&g_map[c0.x * NYNX + c0.z * NX + c0.w], i + 1);
        atomicMax(&g_map[c1.x * NYNX + c1.z * NX + c1.w], i + 2);
        atomicMax(&g_map[c2.x * NYNX + c2.z * NX + c2.w], i + 3);
        atomicMax(&g_map[c3.x * NYNX + c3.z * NX + c3.w], i + 4);
    } else {
        for (int j = i; j < n; j++) {
            int4 c = __ldcs(c4 + j);
            atomicMax(&g_map[c.x * NYNX + c.z * NX + c.w], j + 1);
        }
    }
    cudaTriggerProgrammaticLaunchCompletion();
}

// ---------------------------------------------------------------------------
// Kernel 2: gather + transpose (plateau body; 5 configs pinned at 5.8TB/s
// DRAM = mixed R/W ceiling). PDL gates the g_map read.
// 128-pixel x-tile, 4 stages through a 3-buffer cp.async ring.
// Swizzle: P(xl, c) = xl*128 + ((c>>2 ^ xl) << 2) + (c&3), xl = x % 32.
//   Fill : warp=pixel, lane=quad -> cp.async 16B, conflict-free smem dst.
//   Drain: warp=quad q; lane=(c_sub=lane>>3, xg=lane&7): 4 conflict-free
//          LDS.32 (banks (q^(4xg+i))*4+c_sub distinct per i) -> 1 STG.128
//          (8 lanes = 128B contiguous per channel row, evict-first).
// ---------------------------------------------------------------------------
__device__ __forceinline__ void fill_stage(const float* __restrict__ feat,
                                           float* __restrict__ buf,
                                           const int* __restrict__ vidx,
                                           int s, int warp, int lane) {
    #pragma unroll
    for (int m = 0; m < 2; m++) {
        int xl = warp * 2 + m;                     // 0..31 within stage
        int v  = vidx[s * SPX + xl];
        uint32_t dst = smem_u32(&buf[xl * FEAT_DIM + ((lane ^ xl) << 2)]);
        const float* src = feat + (size_t)(v < 0 ? 0 : v) * FEAT_DIM + lane * 4;
        cp_async16(dst, src, v < 0 ? 0 : 16);      // zfill empties
    }
    cp_commit();
}

__device__ __forceinline__ void drain_stage(float* __restrict__ out,
                                            const float* __restrict__ buf,
                                            size_t pixbase, int s,
                                            int warp, int lane) {
    int c_sub = lane >> 3;                         // 0..3: channel within quad
    int xg    = lane & 7;                          // 0..7: 4-pixel group
    #pragma unroll
    for (int m = 0; m < 2; m++) {
        int q = warp * 2 + m;                      // channel quad 0..31
        float4 val;
        {   // 4 conflict-free LDS.32: x = 4*xg + i, addr = x*128+((q^x)<<2)+c_sub
            int x0l = 4 * xg;
            val.x = buf[(x0l + 0) * FEAT_DIM + ((q ^ (x0l + 0)) << 2) + c_sub];
            val.y = buf[(x0l + 1) * FEAT_DIM + ((q ^ (x0l + 1)) << 2) + c_sub];
            val.z = buf[(x0l + 2) * FEAT_DIM + ((q ^ (x0l + 2)) << 2) + c_sub];
            val.w = buf[(x0l + 3) * FEAT_DIM + ((q ^ (x0l + 3)) << 2) + c_sub];
        }
        int c = 4 * q + c_sub;
        size_t o = pixbase + (size_t)c * NYNX + s * SPX + 4 * xg;
        __stcs(reinterpret_cast<float4*>(out + o), val);   // STG.128, 128B/8 lanes
    }
}

__global__ __launch_bounds__(NTH, 4)
void k_gather(const float* __restrict__ feat, float* __restrict__ out) {
    __shared__ float buf[NBUF][SPX * FEAT_DIM];    // 3 x 16 KB ring
    __shared__ int   vidx[XT];                     // 512 B

    int blk = blockIdx.x;              // 0 .. BATCH*NY*(NX/XT)-1
    int xt  = blk & (NX / XT - 1);     // 0..3
    int y   = (blk >> 2) & (NY - 1);   // 0..511
    int b   = blk >> 11;               // 0..3
    int x0  = xt * XT;

    int t = threadIdx.x, warp = t >> 5, lane = t & 31;

    // Wait for k_argmax to finish before touching g_map (PDL edge).
    cudaGridDependencySynchronize();

    if (t < XT) {
        int idx = b * NYNX + y * NX + x0 + t;
        int v = g_map[idx];
        vidx[t] = v - 1;               // -1 if empty
        if (v) g_map[idx] = 0;         // restore all-zero invariant
    }
    __syncthreads();

    // Prologue: fill stages 0..2 into ring slots 0..2
    #pragma unroll
    for (int s = 0; s < NBUF; s++)
        fill_stage(feat, buf[s], vidx, s, warp, lane);

    size_t pixbase = (size_t)b * FEAT_DIM * NYNX + (size_t)y * NX + x0;

    // s=0: groups pending {0,1,2}; need 0 -> wait<2>
    cp_wait<2>();
    __syncthreads();
    drain_stage(out, buf[0], pixbase, 0, warp, lane);
    __syncthreads();                               // slot 0 free
    fill_stage(feat, buf[0], vidx, 3, warp, lane); // stage 3 -> slot 0

    // s=1: pending {1,2,3}; need 1 -> wait<2>
    cp_wait<2>();
    __syncthreads();
    drain_stage(out, buf[1], pixbase, 1, warp, lane);

    // s=2: pending {2,3}; need 2 -> wait<1>
    cp_wait<1>();
    __syncthreads();
    drain_stage(out, buf[2], pixbase, 2, warp, lane);

    // s=3: pending {3}; -> wait<0>
    cp_wait<0>();
    __syncthreads();
    drain_stage(out, buf[0], pixbase, 3, warp, lane);
}

// ---------------------------------------------------------------------------
extern "C" void kernel_launch(void* const* d_in, const int* in_sizes, int n_in,
                              void* d_out, int out_size) {
    const float* feat  = (const float*)d_in[0];
    const int*   coors = (const int*)d_in[1];
    float*       out   = (float*)d_out;

    int n = in_sizes[0] / FEAT_DIM;   // number of voxels

    // 1) winner per pixel (map is all-zero by invariant)
    k_argmax_map<<<(n / 4 + 511) / 512, 512>>>(coors, n);

    // 2) gather, launched with PDL so its blocks spin up under k_argmax.
    cudaLaunchConfig_t cfg = {};
    cfg.gridDim  = dim3(BATCH * NY * (NX / XT));
    cfg.blockDim = dim3(NTH);
    cfg.stream   = 0;
    cudaLaunchAttribute attr[1];
    attr[0].id = cudaLaunchAttributeProgrammaticStreamSerialization;
    attr[0].val.programmaticStreamSerializationAllowed = 1;
    cfg.attrs    = attr;
    cfg.numAttrs = 1;
    cudaLaunchKernelEx(&cfg, k_gather, feat, out);
}

// round 15
// speedup vs baseline: 1.0982x; 1.0982x over previous
#include <cuda_runtime.h>
#include <stdint.h>

// Problem constants (fixed by the reference problem definition)
#define FEAT_DIM 128
#define BATCH    4
#define NY       512
#define NX       512
#define NYNX     (NY * NX)
#define NPIX     (BATCH * NYNX)      // 1,048,576

#define XT    128      // x-tile per block (4 stages of 32)
#define SPX   32       // pixels per stage
#define NBUF  3        // ring buffers: smem ~50KB -> 4 blocks/SM = 64 warps
#define NTH   512      // 16 warps

// 4 MB scratch: winner map. INVARIANT: all-zero on entry to kernel_launch.
//  - zero at module load (device globals are zero-initialized)
//  - k_argmax writes (voxel_index + 1) via atomicMax (last-write-wins == max idx)
//  - k_gather restores every nonzero entry it consumed back to 0
__device__ int g_map[NPIX];

// ---------------------------------------------------------------------------
// cp.async helpers: 16B global->shared, src_size=0 => zero-fill (empty pixels)
// ---------------------------------------------------------------------------
__device__ __forceinline__ uint32_t smem_u32(const void* p) {
    return (uint32_t)__cvta_generic_to_shared(p);
}
__device__ __forceinline__ void cp_async16(uint32_t dst, const void* src, int src_size) {
    asm volatile("cp.async.cg.shared.global [%0], [%1], 16, %2;\n"
                 :: "r"(dst), "l"(src), "r"(src_size));
}
__device__ __forceinline__ void cp_commit() {
    asm volatile("cp.async.commit_group;\n" ::: "memory");
}
template <int N>
__device__ __forceinline__ void cp_wait() {
    asm volatile("cp.async.wait_group %0;\n" :: "n"(N) : "memory");
}

// ---------------------------------------------------------------------------
// Kernel 1: winner per pixel.  coors: [N,4] int32 (b, z, y, x)
// 512-thread blocks, 2 voxels/thread with BOTH loads issued before either
// atomic (atomicMax result unused -> RED, fire-and-forget). __ldcs: coors is
// touch-once, keep L2 clean for the gather's feat reads.
// ---------------------------------------------------------------------------
__global__ __launch_bounds__(512)
void k_argmax_map(const int* __restrict__ coors, int n) {
    int i = (blockIdx.x * blockDim.x + threadIdx.x) * 2;
    if (i + 1 < n) {
        int4 c0 = __ldcs(reinterpret_cast<const int4*>(coors) + i);
        int4 c1 = __ldcs(reinterpret_cast<const int4*>(coors) + i + 1);
        atomicMax(&g_map[c0.x * NYNX + c0.z * NX + c0.w], i + 1);
        atomicMax(&g_map[c1.x * NYNX + c1.z * NX + c1.w], i + 2);
    } else if (i < n) {
        int4 c0 = __ldcs(reinterpret_cast<const int4*>(coors) + i);
        atomicMax(&g_map[c0.x * NYNX + c0.z * NX + c0.w], i + 1);
    }
    cudaTriggerProgrammaticLaunchCompletion();
}

// ---------------------------------------------------------------------------
// Kernel 2: gather + transpose (champion plateau body: 112.8us, DRAM 73.5%
// -- at the HBM mixed read/write ceiling, confirmed across 5 configs).
// PDL: blocks become resident during k_argmax; cudaGridDependencySynchronize
// gates the g_map read.
// 128-pixel x-tile, 4 stages through a 3-buffer cp.async ring.
// Swizzle: P(xl, c) = xl*128 + ((c>>2 ^ xl) << 2) + (c&3), xl = x % 32.
//   Fill : warp=pixel, lane=quad -> cp.async 16B, conflict-free smem dst
//          (banks (lane^xl)*4.. distinct per lane).
//   Drain: warp covers 2 quads; lane=x-in-stage -> LDS.128 (banks (q^lane)*4
//          distinct per lane: conflict-free) + 4x 128B coalesced STG.32
//          (evict-first: output is touch-once).
// ---------------------------------------------------------------------------
__device__ __forceinline__ void fill_stage(const float* __restrict__ feat,
                                           float* __restrict__ buf,
                                           const int* __restrict__ vidx,
                                           int s, int warp, int lane) {
    #pragma unroll
    for (int m = 0; m < 2; m++) {
        int xl = warp * 2 + m;                     // 0..31 within stage
        int v  = vidx[s * SPX + xl];
        uint32_t dst = smem_u32(&buf[xl * FEAT_DIM + ((lane ^ xl) << 2)]);
        const float* src = feat + (size_t)(v < 0 ? 0 : v) * FEAT_DIM + lane * 4;
        cp_async16(dst, src, v < 0 ? 0 : 16);      // zfill empties
    }
    cp_commit();
}

__device__ __forceinline__ void drain_stage(float* __restrict__ out,
                                            const float* __restrict__ buf,
                                            size_t pixbase, int s,
                                            int warp, int lane) {
    #pragma unroll
    for (int m = 0; m < 2; m++) {
        int q = warp * 2 + m;                      // channel quad 0..31
        float4 val = *reinterpret_cast<const float4*>(
            &buf[lane * FEAT_DIM + ((q ^ lane) << 2)]);     // LDS.128
        size_t o = pixbase + (size_t)(4 * q) * NYNX + s * SPX + lane;
        __stcs(out + o,            val.x);         // 4 x 128B coalesced STG
        __stcs(out + o +     NYNX, val.y);
        __stcs(out + o + 2 * NYNX, val.z);
        __stcs(out + o + 3 * NYNX, val.w);
    }
}

__global__ __launch_bounds__(NTH, 4)
void k_gather(const float* __restrict__ feat, float* __restrict__ out) {
    __shared__ float buf[NBUF][SPX * FEAT_DIM];    // 3 x 16 KB ring
    __shared__ int   vidx[XT];                     // 512 B

    int blk = blockIdx.x;              // 0 .. BATCH*NY*(NX/XT)-1
    int xt  = blk & (NX / XT - 1);     // 0..3
    int y   = (blk >> 2) & (NY - 1);   // 0..511
    int b   = blk >> 11;               // 0..3
    int x0  = xt * XT;

    int t = threadIdx.x, warp = t >> 5, lane = t & 31;

    // Wait for k_argmax to finish before touching g_map (PDL edge).
    cudaGridDependencySynchronize();

    if (t < XT) {
        int idx = b * NYNX + y * NX + x0 + t;
        int v = g_map[idx];
        vidx[t] = v - 1;               // -1 if empty
        if (v) g_map[idx] = 0;         // restore all-zero invariant
    }
    __syncthreads();

    // Prologue: fill stages 0..2 into ring slots 0..2
    #pragma unroll
    for (int s = 0; s < NBUF; s++)
        fill_stage(feat, buf[s], vidx, s, warp, lane);

    size_t pixbase = (size_t)b * FEAT_DIM * NYNX + (size_t)y * NX + x0;

    // s=0: groups pending {0,1,2}; need 0 -> wait<2>
    cp_wait<2>();
    __syncthreads();
    drain_stage(out, buf[0], pixbase, 0, warp, lane);
    __syncthreads();                               // slot 0 free
    fill_stage(feat, buf[0], vidx, 3, warp, lane); // stage 3 -> slot 0

    // s=1: pending {1,2,3}; need 1 -> wait<2>
    cp_wait<2>();
    __syncthreads();
    drain_stage(out, buf[1], pixbase, 1, warp, lane);

    // s=2: pending {2,3}; need 2 -> wait<1>
    cp_wait<1>();
    __syncthreads();
    drain_stage(out, buf[2], pixbase, 2, warp, lane);

    // s=3: pending {3}; -> wait<0>
    cp_wait<0>();
    __syncthreads();
    drain_stage(out, buf[0], pixbase, 3, warp, lane);
}

// ---------------------------------------------------------------------------
extern "C" void kernel_launch(void* const* d_in, const int* in_sizes, int n_in,
                              void* d_out, int out_size) {
    const float* feat  = (const float*)d_in[0];
    const int*   coors = (const int*)d_in[1];
    float*       out   = (float*)d_out;

    int n = in_sizes[0] / FEAT_DIM;   // number of voxels

    // 1) winner per pixel (map is all-zero by invariant)
    k_argmax_map<<<(n / 2 + 511) / 512, 512>>>(coors, n);

    // 2) gather, launched with PDL so its blocks spin up under k_argmax.
    cudaLaunchConfig_t cfg = {};
    cfg.gridDim  = dim3(BATCH * NY * (NX / XT));
    cfg.blockDim = dim3(NTH);
    cfg.stream   = 0;
    cudaLaunchAttribute attr[1];
    attr[0].id = cudaLaunchAttributeProgrammaticStreamSerialization;
    attr[0].val.programmaticStreamSerializationAllowed = 1;
    cfg.attrs    = attr;
    cfg.numAttrs = 1;
    cudaLaunchKernelEx(&cfg, k_gather, feat, out);
}